// round 15
// baseline (speedup 1.0000x reference)
#include <cuda_runtime.h>
#include <cuda_fp16.h>
#include <math.h>
#include <stdint.h>

// ---------------------------------------------------------------------------
// TemporalGraphEuler: knn(8192,10) -> embed(3->256) -> 10x
//   { a1 = mean10(h); a2 = mean10(a1);
//     c = [h|a1|a2] @ [W0;W1;W2]   (fp16 2-term split GEMM via mma.sync)
//     h += 0.1*tanh(c + b);  pred_t = h @ Rw + Rb }   (fused epilogue)
// D = Ahi*Bhi (fp32 acc) + (Alo*2048)*Bhi (fp16 acc, scaled back 1/2048)
// ---------------------------------------------------------------------------

#define N_NODES 8192
#define D_H     256
#define K_TOT   768
#define K_NN    10
#define STEPS   10
#define INF_F (__int_as_float(0x7f800000))
#define LO_SCALE 2048.0f
#define INV_LO_SCALE (1.0f / 2048.0f)

// ---------------- device scratch -------------------------------------------
__device__ float   g_h  [N_NODES * D_H];
__device__ float   g_a1 [N_NODES * D_H];
__device__ __half  g_Ahi[N_NODES * K_TOT];   // [h|a1|a2] fp16 hi split
__device__ __half  g_Alo[N_NODES * K_TOT];   // fp16 lo split, pre-scaled x2048
__device__ __half  g_Bhi[D_H * K_TOT];       // W^T fp16 hi: [n][k]
__device__ int     g_nbr[N_NODES * K_NN];

// ---------------- helpers --------------------------------------------------
__device__ __forceinline__ uint32_t smem_to_u32(const void* p) {
    uint32_t a;
    asm("{ .reg .u64 t; cvta.to.shared.u64 t, %1; cvt.u32.u64 %0, t; }"
        : "=r"(a) : "l"(p));
    return a;
}
#define CP_ASYNC16(dst, src) \
    asm volatile("cp.async.cg.shared.global [%0], [%1], 16;" \
                 :: "r"(dst), "l"(src) : "memory")
#define CP_COMMIT() asm volatile("cp.async.commit_group;" ::: "memory")
#define CP_WAIT1()  asm volatile("cp.async.wait_group 1;" ::: "memory")

__device__ __forceinline__ void ldmx4(uint32_t* r, uint32_t addr) {
    asm volatile("ldmatrix.sync.aligned.m8n8.x4.shared.b16 {%0,%1,%2,%3}, [%4];"
        : "=r"(r[0]), "=r"(r[1]), "=r"(r[2]), "=r"(r[3]) : "r"(addr));
}
// fp32-accumulate HMMA (main term)
__device__ __forceinline__ void mma_f16(float* d, const uint32_t* a,
                                        uint32_t b0, uint32_t b1) {
    asm volatile("mma.sync.aligned.m16n8k16.row.col.f32.f16.f16.f32 "
        "{%0,%1,%2,%3}, {%4,%5,%6,%7}, {%8,%9}, {%0,%1,%2,%3};"
        : "+f"(d[0]), "+f"(d[1]), "+f"(d[2]), "+f"(d[3])
        : "r"(a[0]), "r"(a[1]), "r"(a[2]), "r"(a[3]), "r"(b0), "r"(b1));
}
// fp16-accumulate HMMA (lo correction term, 2x rate)
__device__ __forceinline__ void mma_f16acc(uint32_t* c, const uint32_t* a,
                                           uint32_t b0, uint32_t b1) {
    asm volatile("mma.sync.aligned.m16n8k16.row.col.f16.f16.f16.f16 "
        "{%0,%1}, {%2,%3,%4,%5}, {%6,%7}, {%0,%1};"
        : "+r"(c[0]), "+r"(c[1])
        : "r"(a[0]), "r"(a[1]), "r"(a[2]), "r"(a[3]), "r"(b0), "r"(b1));
}
__device__ __forceinline__ void split_f16(float x, __half& hi, __half& lo) {
    hi = __float2half_rn(x);
    lo = __float2half_rn((x - __half2float(hi)) * LO_SCALE);
}
__device__ __forceinline__ float fast_tanh(float x) {
    return 1.0f - __fdividef(2.0f, __expf(2.0f * x) + 1.0f);
}

// ---------------------------------------------------------------------------
// 0) W^T fp16 hi: g_Bhi(n,k) = fp16(W[k][n]),  W = conv_ws flat [768,256]
// ---------------------------------------------------------------------------
__global__ void prep_w_kernel(const float* __restrict__ W) {
    int idx = blockIdx.x * 256 + threadIdx.x;
    int k = idx >> 8, n = idx & 255;
    g_Bhi[n * K_TOT + k] = __float2half_rn(W[idx]);
}

// ---------------------------------------------------------------------------
// 1) knn — packed float4 computed inline during tile fill
// ---------------------------------------------------------------------------
#define KNN_TILE 1024
__global__ __launch_bounds__(256) void knn_kernel(const float* __restrict__ L) {
    __shared__ float4 tile[KNN_TILE];
    __shared__ float  mbd[32][8 * K_NN];
    __shared__ int    mbi[32][8 * K_NN];

    const int tid  = threadIdx.x;
    const int qloc = tid >> 3;
    const int tq   = tid & 7;
    const int q    = blockIdx.x * 32 + qloc;

    const float qx = L[3 * q + 0], qy = L[3 * q + 1], qz = L[3 * q + 2];

    float dl[K_NN];
    int   il[K_NN];
#pragma unroll
    for (int s = 0; s < K_NN; s++) { dl[s] = INF_F; il[s] = 0; }
    float kk = INF_F;

    for (int t0 = 0; t0 < N_NODES; t0 += KNN_TILE) {
        for (int c = tid; c < KNN_TILE; c += 256) {
            int j = t0 + c;
            float x = L[3 * j + 0], y = L[3 * j + 1], z = L[3 * j + 2];
            tile[c] = make_float4(-2.f * x, -2.f * y, -2.f * z,
                                  x * x + y * y + z * z);
        }
        __syncthreads();
        const int cbase = tq * (KNN_TILE / 8);
#pragma unroll 4
        for (int c = 0; c < KNN_TILE / 8; ++c) {
            float4 p = tile[cbase + c];
            float t = fmaf(p.x, qx, p.w);
            t = fmaf(p.y, qy, t);
            t = fmaf(p.z, qz, t);
            if (t < kk) {
                int j = t0 + cbase + c;
                if (j != q) {
                    bool done = false;
#pragma unroll
                    for (int s = 0; s < K_NN; s++)
                        if (!done && dl[s] == kk) { dl[s] = t; il[s] = j; done = true; }
                    kk = dl[0];
#pragma unroll
                    for (int s = 1; s < K_NN; s++) kk = fmaxf(kk, dl[s]);
                }
            }
        }
        __syncthreads();
    }
#pragma unroll
    for (int s = 0; s < K_NN; s++) {
        mbd[qloc][tq * K_NN + s] = dl[s];
        mbi[qloc][tq * K_NN + s] = il[s];
    }
    __syncthreads();
    if (tid < 32) {
        const int qq = blockIdx.x * 32 + tid;
        for (int r = 0; r < K_NN; r++) {
            float best = INF_F; int bs = 0;
            for (int s = 0; s < 8 * K_NN; s++) {
                float v = mbd[tid][s];
                if (v < best) { best = v; bs = s; }
            }
            g_nbr[qq * K_NN + r] = mbi[tid][bs];
            mbd[tid][bs] = INF_F;
        }
    }
}

// ---------------------------------------------------------------------------
// 2) embedding + initial readout fused
// ---------------------------------------------------------------------------
__global__ __launch_bounds__(256) void embed_readout_kernel(
        const float* __restrict__ L,
        const float* __restrict__ W,
        const float* __restrict__ b,
        const float* __restrict__ rw, const float* __restrict__ rb,
        float* __restrict__ x_out) {
    int i = blockIdx.x, d = threadIdx.x;
    float v = b[d];
    v = fmaf(L[3 * i + 0], W[0 * D_H + d], v);
    v = fmaf(L[3 * i + 1], W[1 * D_H + d], v);
    v = fmaf(L[3 * i + 2], W[2 * D_H + d], v);
    g_h[i * D_H + d] = v;
    __half hi, lo;
    split_f16(v, hi, lo);
    g_Ahi[(size_t)i * K_TOT + d] = hi;
    g_Alo[(size_t)i * K_TOT + d] = lo;

    float p0 = v * rw[d * 3 + 0];
    float p1 = v * rw[d * 3 + 1];
    float p2 = v * rw[d * 3 + 2];
#pragma unroll
    for (int o = 16; o; o >>= 1) {
        p0 += __shfl_down_sync(0xffffffffu, p0, o);
        p1 += __shfl_down_sync(0xffffffffu, p1, o);
        p2 += __shfl_down_sync(0xffffffffu, p2, o);
    }
    __shared__ float red[3][8];
    int w = d >> 5, lane = d & 31;
    if (lane == 0) { red[0][w] = p0; red[1][w] = p1; red[2][w] = p2; }
    __syncthreads();
    if (d < 3) {
        float s = rb[d];
#pragma unroll
        for (int ww = 0; ww < 8; ww++) s += red[d][ww];
        x_out[i * 3 + d] = s;
    }
}

// ---------------------------------------------------------------------------
// 3) aggregation (fp16 split outputs)
// ---------------------------------------------------------------------------
__global__ __launch_bounds__(256) void agg_kernel(int mode) {
    const int node = blockIdx.x * 4 + (threadIdx.x >> 6);
    const int c4   = threadIdx.x & 63;
    const float4* __restrict__ in4 =
        (const float4*)(mode == 0 ? (const float*)g_h : (const float*)g_a1);

    int nb[K_NN];
#pragma unroll
    for (int m = 0; m < K_NN; m++) nb[m] = g_nbr[node * K_NN + m];

    float4 s = make_float4(0.f, 0.f, 0.f, 0.f);
#pragma unroll
    for (int m = 0; m < K_NN; m++) {
        float4 v = in4[(size_t)nb[m] * 64 + c4];
        s.x += v.x; s.y += v.y; s.z += v.z; s.w += v.w;
    }
    float r = rsqrtf(10.0f);
    float nrm = r * r;
    s.x *= nrm; s.y *= nrm; s.z *= nrm; s.w *= nrm;

    if (mode == 0) ((float4*)g_a1)[(size_t)node * 64 + c4] = s;

    const int base = (mode == 0) ? 256 : 512;
    size_t o = (size_t)node * K_TOT + base + c4 * 4;
    __half h0, l0, h1, l1, h2, l2, h3, l3;
    split_f16(s.x, h0, l0); split_f16(s.y, h1, l1);
    split_f16(s.z, h2, l2); split_f16(s.w, h3, l3);
    *(__half2*)&g_Ahi[o + 0] = __halves2half2(h0, h1);
    *(__half2*)&g_Ahi[o + 2] = __halves2half2(h2, h3);
    *(__half2*)&g_Alo[o + 0] = __halves2half2(l0, l1);
    *(__half2*)&g_Alo[o + 2] = __halves2half2(l2, l3);
}

// ---------------------------------------------------------------------------
// 4) fused mma.sync GEMM + Euler update + readout.
//    CTA: 64 rows x 256 cols. K=768, BK=32, double-buffered cp.async.
//    8 warps: 2(M) x 4(N); warp tile 32x64.
//    D = Ahi*Bhi (fp32 acc) + Alo'*Bhi (fp16 acc) * 1/2048
// ---------------------------------------------------------------------------
#define BK        32
#define PAD_ROW   80
#define S_AHI     0
#define S_ALO     (64 * PAD_ROW)                 // 5120
#define S_BHI     (2 * 64 * PAD_ROW)             // 10240
#define STAGE_SZ  (S_BHI + 256 * PAD_ROW)        // 30720
#define GEMM_DSMEM (2 * STAGE_SZ)                // 61440
#define NSTAGES   24

__global__ __launch_bounds__(256) void gemm_fused_kernel(
        const float* __restrict__ conv_b,
        const float* __restrict__ rw, const float* __restrict__ rb,
        float* __restrict__ pred, float* __restrict__ pred2,
        float* __restrict__ hout) {
    extern __shared__ char dsm[];
    __shared__ float s_red[64][4][3];

    const int tid  = threadIdx.x;
    const int wid  = tid >> 5;
    const int lane = tid & 31;
    const int wm   = wid & 1;
    const int wn   = wid >> 1;
    const int bm   = blockIdx.x * 64;

    const uint32_t smem_base = smem_to_u32(dsm);

    auto load_stage = [&](int kt, int sb) {
        const uint32_t st = smem_base + sb * STAGE_SZ;
        const int k0 = kt * BK;
        {   // A hi+lo: 64 rows x 4 chunks of 16B
            int r = tid >> 2, c = tid & 3;
            uint32_t dst = st + r * PAD_ROW + c * 16;
            size_t gidx = (size_t)(bm + r) * K_TOT + k0 + c * 8;
            CP_ASYNC16(dst + S_AHI, &g_Ahi[gidx]);
            CP_ASYNC16(dst + S_ALO, &g_Alo[gidx]);
        }
#pragma unroll
        for (int it = 0; it < 4; ++it) {   // B hi: 256 rows x 4 chunks
            int u = tid + it * 256;
            int r = u >> 2, c = u & 3;
            uint32_t dst = st + r * PAD_ROW + c * 16;
            size_t gidx = (size_t)r * K_TOT + k0 + c * 8;
            CP_ASYNC16(dst + S_BHI, &g_Bhi[gidx]);
        }
    };

    float acc[2][8][4];
    uint32_t acc2[2][8][2];
#pragma unroll
    for (int i = 0; i < 2; i++)
#pragma unroll
        for (int j = 0; j < 8; j++) {
#pragma unroll
            for (int k = 0; k < 4; k++) acc[i][j][k] = 0.f;
            acc2[i][j][0] = 0u; acc2[i][j][1] = 0u;
        }

    load_stage(0, 0); CP_COMMIT();
    load_stage(1, 1); CP_COMMIT();

    const int r16   = lane & 15;
    const int chalf = lane >> 4;

#pragma unroll 1
    for (int kt = 0; kt < NSTAGES; ++kt) {
        const int sb = kt & 1;
        CP_WAIT1();
        __syncthreads();
        const uint32_t st = smem_base + sb * STAGE_SZ;

#pragma unroll
        for (int kh = 0; kh < 2; ++kh) {
            const uint32_t koff = kh * 32 + chalf * 16;
            uint32_t ahi[2][4], alo[2][4], bhi[4][4];
#pragma unroll
            for (int mt = 0; mt < 2; ++mt) {
                uint32_t ra = st + (wm * 32 + mt * 16 + r16) * PAD_ROW + koff;
                ldmx4(ahi[mt], ra + S_AHI);
                ldmx4(alo[mt], ra + S_ALO);
            }
#pragma unroll
            for (int np = 0; np < 4; ++np) {
                uint32_t rb_ = st + (wn * 64 + np * 16 + r16) * PAD_ROW + koff;
                ldmx4(bhi[np], rb_ + S_BHI);
            }
            // main term: fp32 accumulate
#pragma unroll
            for (int mt = 0; mt < 2; ++mt)
#pragma unroll
                for (int np = 0; np < 4; ++np) {
                    mma_f16(acc[mt][np * 2 + 0], ahi[mt], bhi[np][0], bhi[np][2]);
                    mma_f16(acc[mt][np * 2 + 1], ahi[mt], bhi[np][1], bhi[np][3]);
                }
            // lo correction: fp16 accumulate (2x rate), values pre-scaled x2048
#pragma unroll
            for (int mt = 0; mt < 2; ++mt)
#pragma unroll
                for (int np = 0; np < 4; ++np) {
                    mma_f16acc(acc2[mt][np * 2 + 0], alo[mt], bhi[np][0], bhi[np][2]);
                    mma_f16acc(acc2[mt][np * 2 + 1], alo[mt], bhi[np][1], bhi[np][3]);
                }
        }
        __syncthreads();
        if (kt + 2 < NSTAGES) load_stage(kt + 2, sb);
        CP_COMMIT();
    }

    // ---- epilogue --------------------------------------------------------
    float p[4][3];
#pragma unroll
    for (int i = 0; i < 4; i++) { p[i][0] = p[i][1] = p[i][2] = 0.f; }

#pragma unroll
    for (int mt = 0; mt < 2; ++mt)
#pragma unroll
        for (int rh = 0; rh < 2; ++rh) {
            const int rowL = wm * 32 + mt * 16 + rh * 8 + (lane >> 2);
            const int row  = bm + rowL;
            float* __restrict__ hrow = &g_h[(size_t)row * D_H];
            __half* __restrict__ hirow = &g_Ahi[(size_t)row * K_TOT];
            __half* __restrict__ lorow = &g_Alo[(size_t)row * K_TOT];
            float* pp = p[mt * 2 + rh];
#pragma unroll
            for (int nt = 0; nt < 8; ++nt) {
                const int col = wn * 64 + nt * 8 + 2 * (lane & 3);
                __half2 lo2 = *(__half2*)&acc2[mt][nt][rh];
                float v0 = fmaf(__low2float(lo2),  INV_LO_SCALE, acc[mt][nt][rh * 2 + 0]);
                float v1 = fmaf(__high2float(lo2), INV_LO_SCALE, acc[mt][nt][rh * 2 + 1]);
                float cv0 = v0 + __ldg(&conv_b[col]);
                float cv1 = v1 + __ldg(&conv_b[col + 1]);
                float2 hv = *(float2*)&hrow[col];
                float hn0 = fmaf(0.1f, fast_tanh(cv0), hv.x);
                float hn1 = fmaf(0.1f, fast_tanh(cv1), hv.y);
                *(float2*)&hrow[col] = make_float2(hn0, hn1);
                if (hout) *(float2*)&hout[(size_t)row * D_H + col] = make_float2(hn0, hn1);
                __half bh0, bl0, bh1, bl1;
                split_f16(hn0, bh0, bl0); split_f16(hn1, bh1, bl1);
                *(__half2*)&hirow[col] = __halves2half2(bh0, bh1);
                *(__half2*)&lorow[col] = __halves2half2(bl0, bl1);
                pp[0] = fmaf(hn0, __ldg(&rw[col * 3 + 0]), pp[0]);
                pp[1] = fmaf(hn0, __ldg(&rw[col * 3 + 1]), pp[1]);
                pp[2] = fmaf(hn0, __ldg(&rw[col * 3 + 2]), pp[2]);
                pp[0] = fmaf(hn1, __ldg(&rw[col * 3 + 3]), pp[0]);
                pp[1] = fmaf(hn1, __ldg(&rw[col * 3 + 4]), pp[1]);
                pp[2] = fmaf(hn1, __ldg(&rw[col * 3 + 5]), pp[2]);
            }
        }

#pragma unroll
    for (int i = 0; i < 4; i++)
#pragma unroll
        for (int c = 0; c < 3; c++) {
            p[i][c] += __shfl_xor_sync(0xffffffffu, p[i][c], 1);
            p[i][c] += __shfl_xor_sync(0xffffffffu, p[i][c], 2);
        }
    if ((lane & 3) == 0) {
#pragma unroll
        for (int mt = 0; mt < 2; ++mt)
#pragma unroll
            for (int rh = 0; rh < 2; ++rh) {
                const int rowL = wm * 32 + mt * 16 + rh * 8 + (lane >> 2);
#pragma unroll
                for (int c = 0; c < 3; c++)
                    s_red[rowL][wn][c] = p[mt * 2 + rh][c];
            }
    }
    __syncthreads();
    if (tid < 192) {
        const int rowL = tid / 3, c = tid % 3;
        float s = __ldg(&rb[c]) + s_red[rowL][0][c] + s_red[rowL][1][c]
                                + s_red[rowL][2][c] + s_red[rowL][3][c];
        const int row = bm + rowL;
        pred[row * 3 + c] = s;
        if (pred2) pred2[row * 3 + c] = s;
    }
}

// ---------------------------------------------------------------------------
// launch — ordered so gemm_fused is launch #6 (ncu -s 5 -c 1 capture target)
// ---------------------------------------------------------------------------
extern "C" void kernel_launch(void* const* d_in, const int* in_sizes, int n_in,
                              void* d_out, int out_size) {
    const float* landmarks = (const float*)d_in[0];
    const float* emb_w     = (const float*)d_in[1];
    const float* emb_b     = (const float*)d_in[2];
    const float* readout_w = (const float*)d_in[3];
    const float* readout_b = (const float*)d_in[4];
    const float* conv_ws   = (const float*)d_in[5];
    const float* conv_b    = (const float*)d_in[6];

    float* out = (float*)d_out;
    float* y_out  = out;                               // [8192,3]
    float* h_out  = out + N_NODES * 3;                 // [8192,256]
    float* x_out  = h_out + N_NODES * D_H;             // [8192,3]
    float* lp_out = x_out + N_NODES * 3;               // [10,8192,3]

    cudaFuncSetAttribute(gemm_fused_kernel,
                         cudaFuncAttributeMaxDynamicSharedMemorySize, GEMM_DSMEM);

    prep_w_kernel<<<K_TOT, 256>>>(conv_ws);                                  // 1
    knn_kernel<<<N_NODES / 32, 256>>>(landmarks);                            // 2
    embed_readout_kernel<<<N_NODES, D_H>>>(landmarks, emb_w, emb_b,
                                           readout_w, readout_b, x_out);     // 3

    for (int t = 0; t < STEPS; ++t) {
        agg_kernel<<<N_NODES / 4, 256>>>(0);                                 // 4
        agg_kernel<<<N_NODES / 4, 256>>>(1);                                 // 5
        float* pred2 = (t == STEPS - 1) ? y_out : nullptr;
        float* hh    = (t == STEPS - 1) ? h_out : nullptr;
        gemm_fused_kernel<<<N_NODES / 64, 256, GEMM_DSMEM>>>(                // 6
            conv_b, readout_w, readout_b,
            lp_out + (size_t)t * N_NODES * 3, pred2, hh);
    }
}

// round 17
// speedup vs baseline: 1.0552x; 1.0552x over previous
#include <cuda_runtime.h>
#include <cuda_fp16.h>
#include <math.h>
#include <stdint.h>

// ---------------------------------------------------------------------------
// TemporalGraphEuler: knn(8192,10) -> embed(3->256) -> 10x
//   { a1 = mean10(h); a2 = mean10(a1);
//     c = [h|a1|a2] @ [W0;W1;W2]   (fp16 2-term split GEMM via mma.sync)
//     h += 0.1*tanh(c + b);  pred_t = h @ Rw + Rb }   (fused epilogue)
// D = Ahi*Bhi + Alo*Bhi, both fp32 accumulate.
// Aggregation gathers the fp16 hi panel (halves L2 bytes, err ~2^-12).
// ---------------------------------------------------------------------------

#define N_NODES 8192
#define D_H     256
#define K_TOT   768
#define K_NN    10
#define STEPS   10
#define INF_F (__int_as_float(0x7f800000))

// ---------------- device scratch -------------------------------------------
__device__ float   g_h  [N_NODES * D_H];
__device__ __half  g_Ahi[N_NODES * K_TOT];   // [h|a1|a2] fp16 hi split
__device__ __half  g_Alo[N_NODES * K_TOT];   // fp16 lo split
__device__ __half  g_Bhi[D_H * K_TOT];       // W^T fp16 hi: [n][k]
__device__ int     g_nbr[N_NODES * K_NN];

// ---------------- helpers --------------------------------------------------
__device__ __forceinline__ uint32_t smem_to_u32(const void* p) {
    uint32_t a;
    asm("{ .reg .u64 t; cvta.to.shared.u64 t, %1; cvt.u32.u64 %0, t; }"
        : "=r"(a) : "l"(p));
    return a;
}
#define CP_ASYNC16(dst, src) \
    asm volatile("cp.async.cg.shared.global [%0], [%1], 16;" \
                 :: "r"(dst), "l"(src) : "memory")
#define CP_COMMIT() asm volatile("cp.async.commit_group;" ::: "memory")
#define CP_WAIT1()  asm volatile("cp.async.wait_group 1;" ::: "memory")

__device__ __forceinline__ void ldmx4(uint32_t* r, uint32_t addr) {
    asm volatile("ldmatrix.sync.aligned.m8n8.x4.shared.b16 {%0,%1,%2,%3}, [%4];"
        : "=r"(r[0]), "=r"(r[1]), "=r"(r[2]), "=r"(r[3]) : "r"(addr));
}
__device__ __forceinline__ void mma_f16(float* d, const uint32_t* a,
                                        uint32_t b0, uint32_t b1) {
    asm volatile("mma.sync.aligned.m16n8k16.row.col.f32.f16.f16.f32 "
        "{%0,%1,%2,%3}, {%4,%5,%6,%7}, {%8,%9}, {%0,%1,%2,%3};"
        : "+f"(d[0]), "+f"(d[1]), "+f"(d[2]), "+f"(d[3])
        : "r"(a[0]), "r"(a[1]), "r"(a[2]), "r"(a[3]), "r"(b0), "r"(b1));
}
__device__ __forceinline__ void split_f16(float x, __half& hi, __half& lo) {
    hi = __float2half_rn(x);
    lo = __float2half_rn(x - __half2float(hi));
}
__device__ __forceinline__ float fast_tanh(float x) {
    return 1.0f - __fdividef(2.0f, __expf(2.0f * x) + 1.0f);
}

// ---------------------------------------------------------------------------
// 0) W^T fp16 hi: g_Bhi(n,k) = fp16(W[k][n]),  W = conv_ws flat [768,256]
// ---------------------------------------------------------------------------
__global__ void prep_w_kernel(const float* __restrict__ W) {
    int idx = blockIdx.x * 256 + threadIdx.x;
    int k = idx >> 8, n = idx & 255;
    g_Bhi[n * K_TOT + k] = __float2half_rn(W[idx]);
}

// ---------------------------------------------------------------------------
// 1) knn — packed float4 computed inline during tile fill
// ---------------------------------------------------------------------------
#define KNN_TILE 1024
__global__ __launch_bounds__(256) void knn_kernel(const float* __restrict__ L) {
    __shared__ float4 tile[KNN_TILE];
    __shared__ float  mbd[32][8 * K_NN];
    __shared__ int    mbi[32][8 * K_NN];

    const int tid  = threadIdx.x;
    const int qloc = tid >> 3;
    const int tq   = tid & 7;
    const int q    = blockIdx.x * 32 + qloc;

    const float qx = L[3 * q + 0], qy = L[3 * q + 1], qz = L[3 * q + 2];

    float dl[K_NN];
    int   il[K_NN];
#pragma unroll
    for (int s = 0; s < K_NN; s++) { dl[s] = INF_F; il[s] = 0; }
    float kk = INF_F;

    for (int t0 = 0; t0 < N_NODES; t0 += KNN_TILE) {
        for (int c = tid; c < KNN_TILE; c += 256) {
            int j = t0 + c;
            float x = L[3 * j + 0], y = L[3 * j + 1], z = L[3 * j + 2];
            tile[c] = make_float4(-2.f * x, -2.f * y, -2.f * z,
                                  x * x + y * y + z * z);
        }
        __syncthreads();
        const int cbase = tq * (KNN_TILE / 8);
#pragma unroll 4
        for (int c = 0; c < KNN_TILE / 8; ++c) {
            float4 p = tile[cbase + c];
            float t = fmaf(p.x, qx, p.w);
            t = fmaf(p.y, qy, t);
            t = fmaf(p.z, qz, t);
            if (t < kk) {
                int j = t0 + cbase + c;
                if (j != q) {
                    bool done = false;
#pragma unroll
                    for (int s = 0; s < K_NN; s++)
                        if (!done && dl[s] == kk) { dl[s] = t; il[s] = j; done = true; }
                    kk = dl[0];
#pragma unroll
                    for (int s = 1; s < K_NN; s++) kk = fmaxf(kk, dl[s]);
                }
            }
        }
        __syncthreads();
    }
#pragma unroll
    for (int s = 0; s < K_NN; s++) {
        mbd[qloc][tq * K_NN + s] = dl[s];
        mbi[qloc][tq * K_NN + s] = il[s];
    }
    __syncthreads();
    if (tid < 32) {
        const int qq = blockIdx.x * 32 + tid;
        for (int r = 0; r < K_NN; r++) {
            float best = INF_F; int bs = 0;
            for (int s = 0; s < 8 * K_NN; s++) {
                float v = mbd[tid][s];
                if (v < best) { best = v; bs = s; }
            }
            g_nbr[qq * K_NN + r] = mbi[tid][bs];
            mbd[tid][bs] = INF_F;
        }
    }
}

// ---------------------------------------------------------------------------
// 2) embedding + initial readout fused
// ---------------------------------------------------------------------------
__global__ __launch_bounds__(256) void embed_readout_kernel(
        const float* __restrict__ L,
        const float* __restrict__ W,
        const float* __restrict__ b,
        const float* __restrict__ rw, const float* __restrict__ rb,
        float* __restrict__ x_out) {
    int i = blockIdx.x, d = threadIdx.x;
    float v = b[d];
    v = fmaf(L[3 * i + 0], W[0 * D_H + d], v);
    v = fmaf(L[3 * i + 1], W[1 * D_H + d], v);
    v = fmaf(L[3 * i + 2], W[2 * D_H + d], v);
    g_h[i * D_H + d] = v;
    __half hi, lo;
    split_f16(v, hi, lo);
    g_Ahi[(size_t)i * K_TOT + d] = hi;
    g_Alo[(size_t)i * K_TOT + d] = lo;

    float p0 = v * rw[d * 3 + 0];
    float p1 = v * rw[d * 3 + 1];
    float p2 = v * rw[d * 3 + 2];
#pragma unroll
    for (int o = 16; o; o >>= 1) {
        p0 += __shfl_down_sync(0xffffffffu, p0, o);
        p1 += __shfl_down_sync(0xffffffffu, p1, o);
        p2 += __shfl_down_sync(0xffffffffu, p2, o);
    }
    __shared__ float red[3][8];
    int w = d >> 5, lane = d & 31;
    if (lane == 0) { red[0][w] = p0; red[1][w] = p1; red[2][w] = p2; }
    __syncthreads();
    if (d < 3) {
        float s = rb[d];
#pragma unroll
        for (int ww = 0; ww < 8; ww++) s += red[d][ww];
        x_out[i * 3 + d] = s;
    }
}

// ---------------------------------------------------------------------------
// 3) aggregation on fp16 hi panel: out cols = mean10 of in cols (gather).
//    mode0: Ahi[0:256) -> cols 256-511 ; mode1: Ahi[256:512) -> cols 512-767
//    32 threads/node (int4 = 8 halves each), 8 nodes/block.
// ---------------------------------------------------------------------------
__global__ __launch_bounds__(256) void agg_kernel(int mode) {
    const int node = blockIdx.x * 8 + (threadIdx.x >> 5);
    const int seg  = threadIdx.x & 31;           // 8 halves per thread
    const int inb  = (mode == 0) ? 0 : 256;
    const int outb = (mode == 0) ? 256 : 512;

    int nb[K_NN];
#pragma unroll
    for (int m = 0; m < K_NN; m++) nb[m] = g_nbr[node * K_NN + m];

    float s[8];
#pragma unroll
    for (int j = 0; j < 8; j++) s[j] = 0.f;

#pragma unroll
    for (int m = 0; m < K_NN; m++) {
        const __half* row = &g_Ahi[(size_t)nb[m] * K_TOT + inb + seg * 8];
        int4 v = *(const int4*)row;
        __half2 h0 = *(__half2*)&v.x, h1 = *(__half2*)&v.y;
        __half2 h2 = *(__half2*)&v.z, h3 = *(__half2*)&v.w;
        float2 f0 = __half22float2(h0), f1 = __half22float2(h1);
        float2 f2 = __half22float2(h2), f3 = __half22float2(h3);
        s[0] += f0.x; s[1] += f0.y; s[2] += f1.x; s[3] += f1.y;
        s[4] += f2.x; s[5] += f2.y; s[6] += f3.x; s[7] += f3.y;
    }
    float r = rsqrtf(10.0f);
    float nrm = r * r;

    __half hi[8], lo[8];
#pragma unroll
    for (int j = 0; j < 8; j++) split_f16(s[j] * nrm, hi[j], lo[j]);

    size_t o = (size_t)node * K_TOT + outb + seg * 8;
    int4 vh, vl;
    *(__half2*)&vh.x = __halves2half2(hi[0], hi[1]);
    *(__half2*)&vh.y = __halves2half2(hi[2], hi[3]);
    *(__half2*)&vh.z = __halves2half2(hi[4], hi[5]);
    *(__half2*)&vh.w = __halves2half2(hi[6], hi[7]);
    *(__half2*)&vl.x = __halves2half2(lo[0], lo[1]);
    *(__half2*)&vl.y = __halves2half2(lo[2], lo[3]);
    *(__half2*)&vl.z = __halves2half2(lo[4], lo[5]);
    *(__half2*)&vl.w = __halves2half2(lo[6], lo[7]);
    *(int4*)&g_Ahi[o] = vh;
    *(int4*)&g_Alo[o] = vl;
}

// ---------------------------------------------------------------------------
// 4) fused mma.sync GEMM + Euler update + readout.
//    CTA: 64 rows x 256 cols, 512 threads / 16 warps (4M x 4N), warp 16x64.
//    K=768, BK=32, double-buffered cp.async. D = Ahi*Bhi + Alo*Bhi (fp32 acc).
// ---------------------------------------------------------------------------
#define BK        32
#define PAD_ROW   80
#define S_AHI     0
#define S_ALO     (64 * PAD_ROW)                 // 5120
#define S_BHI     (2 * 64 * PAD_ROW)             // 10240
#define STAGE_SZ  (S_BHI + 256 * PAD_ROW)        // 30720
#define GEMM_DSMEM (2 * STAGE_SZ)                // 61440
#define NSTAGES   24

__global__ __launch_bounds__(512) void gemm_fused_kernel(
        const float* __restrict__ conv_b,
        const float* __restrict__ rw, const float* __restrict__ rb,
        float* __restrict__ pred, float* __restrict__ pred2,
        float* __restrict__ hout) {
    extern __shared__ char dsm[];
    __shared__ float s_red[64][4][3];

    const int tid  = threadIdx.x;
    const int wid  = tid >> 5;
    const int lane = tid & 31;
    const int wm   = wid & 3;        // 4 M warps (16 rows each)
    const int wn   = wid >> 2;       // 4 N warps (64 cols each)
    const int bm   = blockIdx.x * 64;

    const uint32_t smem_base = smem_to_u32(dsm);

    auto load_stage = [&](int kt, int sb) {
        const uint32_t st = smem_base + sb * STAGE_SZ;
        const int k0 = kt * BK;
        if (tid < 256) {   // A hi+lo: 64 rows x 4 chunks of 16B
            int r = tid >> 2, c = tid & 3;
            uint32_t dst = st + r * PAD_ROW + c * 16;
            size_t gidx = (size_t)(bm + r) * K_TOT + k0 + c * 8;
            CP_ASYNC16(dst + S_AHI, &g_Ahi[gidx]);
            CP_ASYNC16(dst + S_ALO, &g_Alo[gidx]);
        }
#pragma unroll
        for (int it = 0; it < 2; ++it) {   // B hi: 256 rows x 4 chunks
            int u = tid + it * 512;
            int r = u >> 2, c = u & 3;
            uint32_t dst = st + r * PAD_ROW + c * 16;
            size_t gidx = (size_t)r * K_TOT + k0 + c * 8;
            CP_ASYNC16(dst + S_BHI, &g_Bhi[gidx]);
        }
    };

    float acc[8][4];
#pragma unroll
    for (int j = 0; j < 8; j++)
#pragma unroll
        for (int k = 0; k < 4; k++) acc[j][k] = 0.f;

    load_stage(0, 0); CP_COMMIT();
    load_stage(1, 1); CP_COMMIT();

    const int r16   = lane & 15;
    const int chalf = lane >> 4;

#pragma unroll 1
    for (int kt = 0; kt < NSTAGES; ++kt) {
        const int sb = kt & 1;
        CP_WAIT1();
        __syncthreads();
        const uint32_t st = smem_base + sb * STAGE_SZ;

#pragma unroll
        for (int kh = 0; kh < 2; ++kh) {
            const uint32_t koff = kh * 32 + chalf * 16;
            uint32_t ahi[4], alo[4], bhi[4][4];
            {
                uint32_t ra = st + (wm * 16 + r16) * PAD_ROW + koff;
                ldmx4(ahi, ra + S_AHI);
                ldmx4(alo, ra + S_ALO);
            }
#pragma unroll
            for (int np = 0; np < 4; ++np) {
                uint32_t rb_ = st + (wn * 64 + np * 16 + r16) * PAD_ROW + koff;
                ldmx4(bhi[np], rb_ + S_BHI);
            }
#pragma unroll
            for (int np = 0; np < 4; ++np) {
                mma_f16(acc[np * 2 + 0], ahi, bhi[np][0], bhi[np][2]);
                mma_f16(acc[np * 2 + 1], ahi, bhi[np][1], bhi[np][3]);
            }
#pragma unroll
            for (int np = 0; np < 4; ++np) {
                mma_f16(acc[np * 2 + 0], alo, bhi[np][0], bhi[np][2]);
                mma_f16(acc[np * 2 + 1], alo, bhi[np][1], bhi[np][3]);
            }
        }
        __syncthreads();
        if (kt + 2 < NSTAGES) load_stage(kt + 2, sb);
        CP_COMMIT();
    }

    // ---- epilogue: warp owns rows wm*16..+16, cols wn*64..+64 ------------
    float p[2][3];
#pragma unroll
    for (int i = 0; i < 2; i++) { p[i][0] = p[i][1] = p[i][2] = 0.f; }

#pragma unroll
    for (int rh = 0; rh < 2; ++rh) {
        const int rowL = wm * 16 + rh * 8 + (lane >> 2);
        const int row  = bm + rowL;
        float* __restrict__ hrow = &g_h[(size_t)row * D_H];
        __half* __restrict__ hirow = &g_Ahi[(size_t)row * K_TOT];
        __half* __restrict__ lorow = &g_Alo[(size_t)row * K_TOT];
        float* pp = p[rh];
#pragma unroll
        for (int nt = 0; nt < 8; ++nt) {
            const int col = wn * 64 + nt * 8 + 2 * (lane & 3);
            float cv0 = acc[nt][rh * 2 + 0] + __ldg(&conv_b[col]);
            float cv1 = acc[nt][rh * 2 + 1] + __ldg(&conv_b[col + 1]);
            float2 hv = *(float2*)&hrow[col];
            float hn0 = fmaf(0.1f, fast_tanh(cv0), hv.x);
            float hn1 = fmaf(0.1f, fast_tanh(cv1), hv.y);
            *(float2*)&hrow[col] = make_float2(hn0, hn1);
            if (hout) *(float2*)&hout[(size_t)row * D_H + col] = make_float2(hn0, hn1);
            __half bh0, bl0, bh1, bl1;
            split_f16(hn0, bh0, bl0); split_f16(hn1, bh1, bl1);
            *(__half2*)&hirow[col] = __halves2half2(bh0, bh1);
            *(__half2*)&lorow[col] = __halves2half2(bl0, bl1);
            pp[0] = fmaf(hn0, __ldg(&rw[col * 3 + 0]), pp[0]);
            pp[1] = fmaf(hn0, __ldg(&rw[col * 3 + 1]), pp[1]);
            pp[2] = fmaf(hn0, __ldg(&rw[col * 3 + 2]), pp[2]);
            pp[0] = fmaf(hn1, __ldg(&rw[col * 3 + 3]), pp[0]);
            pp[1] = fmaf(hn1, __ldg(&rw[col * 3 + 4]), pp[1]);
            pp[2] = fmaf(hn1, __ldg(&rw[col * 3 + 5]), pp[2]);
        }
    }

#pragma unroll
    for (int i = 0; i < 2; i++)
#pragma unroll
        for (int c = 0; c < 3; c++) {
            p[i][c] += __shfl_xor_sync(0xffffffffu, p[i][c], 1);
            p[i][c] += __shfl_xor_sync(0xffffffffu, p[i][c], 2);
        }
    if ((lane & 3) == 0) {
#pragma unroll
        for (int rh = 0; rh < 2; ++rh) {
            const int rowL = wm * 16 + rh * 8 + (lane >> 2);
#pragma unroll
            for (int c = 0; c < 3; c++)
                s_red[rowL][wn][c] = p[rh][c];
        }
    }
    __syncthreads();
    if (tid < 192) {
        const int rowL = tid / 3, c = tid % 3;
        float s = __ldg(&rb[c]) + s_red[rowL][0][c] + s_red[rowL][1][c]
                                + s_red[rowL][2][c] + s_red[rowL][3][c];
        const int row = bm + rowL;
        pred[row * 3 + c] = s;
        if (pred2) pred2[row * 3 + c] = s;
    }
}

// ---------------------------------------------------------------------------
// launch — gemm_fused is launch #6 (ncu -s 5 -c 1 capture target)
// ---------------------------------------------------------------------------
extern "C" void kernel_launch(void* const* d_in, const int* in_sizes, int n_in,
                              void* d_out, int out_size) {
    const float* landmarks = (const float*)d_in[0];
    const float* emb_w     = (const float*)d_in[1];
    const float* emb_b     = (const float*)d_in[2];
    const float* readout_w = (const float*)d_in[3];
    const float* readout_b = (const float*)d_in[4];
    const float* conv_ws   = (const float*)d_in[5];
    const float* conv_b    = (const float*)d_in[6];

    float* out = (float*)d_out;
    float* y_out  = out;                               // [8192,3]
    float* h_out  = out + N_NODES * 3;                 // [8192,256]
    float* x_out  = h_out + N_NODES * D_H;             // [8192,3]
    float* lp_out = x_out + N_NODES * 3;               // [10,8192,3]

    cudaFuncSetAttribute(gemm_fused_kernel,
                         cudaFuncAttributeMaxDynamicSharedMemorySize, GEMM_DSMEM);

    prep_w_kernel<<<K_TOT, 256>>>(conv_ws);                                  // 1
    knn_kernel<<<N_NODES / 32, 256>>>(landmarks);                            // 2
    embed_readout_kernel<<<N_NODES, D_H>>>(landmarks, emb_w, emb_b,
                                           readout_w, readout_b, x_out);     // 3

    for (int t = 0; t < STEPS; ++t) {
        agg_kernel<<<N_NODES / 8, 256>>>(0);                                 // 4
        agg_kernel<<<N_NODES / 8, 256>>>(1);                                 // 5
        float* pred2 = (t == STEPS - 1) ? y_out : nullptr;
        float* hh    = (t == STEPS - 1) ? h_out : nullptr;
        gemm_fused_kernel<<<N_NODES / 64, 512, GEMM_DSMEM>>>(                // 6
            conv_b, readout_w, readout_b,
            lp_out + (size_t)t * N_NODES * 3, pred2, hh);
    }
}